// round 11
// baseline (speedup 1.0000x reference)
#include <cuda_runtime.h>
#include <cuda_fp16.h>
#include <cstdint>
#include <math.h>

#define BATCH 16
#define H 209
#define W 133
#define CI 64
#define CO 128
#define NTAP 19
#define OHH 201
#define OWW 129

// hex_indices(2) order (t matches sparse_weights layout) — validated in R1
__constant__ int c_dh[NTAP] = {4,3,5,6,5,3,2,1,2,4,6,7,8,7,6,4,2,1,0};
__constant__ int c_dw[NTAP] = {2,3,3,2,1,1,2,3,4,4,4,3,2,1,0,0,0,1,2};

// prepped weights: [t][co][ci] fp16
__device__ __align__(16) __half g_w[NTAP*CO*CI];

__device__ __forceinline__ uint32_t smem_u32(const void* p) {
    uint32_t a;
    asm("{ .reg .u64 t; cvta.to.shared.u64 t, %1; cvt.u32.u64 %0, t; }" : "=r"(a) : "l"(p));
    return a;
}
__device__ __forceinline__ uint32_t pack2h(__half a, __half b) {
    return (uint32_t)__half_as_ushort(a) | ((uint32_t)__half_as_ushort(b) << 16);
}
__device__ __forceinline__ uint2 cvt4(float4 v) {
    return make_uint2(pack2h(__float2half_rn(v.x), __float2half_rn(v.y)),
                      pack2h(__float2half_rn(v.z), __float2half_rn(v.w)));
}

#define LDSM4(r, addr)                                                          \
    asm volatile("ldmatrix.sync.aligned.m8n8.x4.shared.b16 {%0,%1,%2,%3}, [%4];"\
        : "=r"((r)[0]), "=r"((r)[1]), "=r"((r)[2]), "=r"((r)[3]) : "r"(addr))

#define MMA16816(c, a, b0, b1)                                                  \
    asm volatile("mma.sync.aligned.m16n8k16.row.col.f32.f16.f16.f32 "           \
        "{%0,%1,%2,%3}, {%4,%5,%6,%7}, {%8,%9}, {%0,%1,%2,%3};"                 \
        : "+f"((c)[0]), "+f"((c)[1]), "+f"((c)[2]), "+f"((c)[3])                \
        : "r"((a)[0]), "r"((a)[1]), "r"((a)[2]), "r"((a)[3]), "r"(b0), "r"(b1))

// ---------------- prep: weights to fp16, layout [t][co][ci] ----------------
__global__ void prep_w_kernel(const float* __restrict__ sw) {
    int i = blockIdx.x * blockDim.x + threadIdx.x;
    if (i >= NTAP*CO*CI) return;
    int ci = i & 63;
    int co = (i >> 6) & 127;
    int t  = i >> 13;
    g_w[i] = __float2half_rn(sw[(ci*CO + co)*NTAP + t]);
}

// ---------------- main mma.sync kernel ----------------
// grid (52, 16), 512 threads (16 warps: 4 M x 4 N). PITCH-144 additive layout.
// A: fp16 x-slab in smem, built once, ONE barrier total.
// B: ldmatrix eliminated — fragments loaded straight from g_w (L2-resident)
//    via per-lane LDG.32, ping-pong prefetched one ks-step ahead.
// NO cp.async, NO barriers in the tap loop: warps free-run.
#define PITCH       144
#define SLAB_WC     68
#define SLAB_SLOTS  (12*SLAB_WC)            // 816 (conv)  | edge uses 5*132=660
#define SLAB_BYTES  (SLAB_SLOTS*PITCH)      // 117504
#define SMEM_TOTAL  (SLAB_BYTES + 512)

__global__ __launch_bounds__(512, 1)
void conv_mma_kernel(const float* __restrict__ x,
                     const float* __restrict__ off, float* __restrict__ out) {
    extern __shared__ __align__(1024) char smem[];
    const uint32_t smem_base = smem_u32(smem);
    const int tid    = threadIdx.x;
    const int lane   = tid & 31;
    const int wid    = tid >> 5;
    const int warp_m = wid >> 2;       // 0..3
    const int warp_n = wid & 3;        // 0..3
    const int b      = blockIdx.y;
    const bool is_edge = (blockIdx.x == 51);
    const int r0     = blockIdx.x * 4; // first output row (conv path)

    float* s_off = (float*)(smem + SLAB_BYTES);
    if (tid < CO) s_off[tid] = off[tid];

    const float* xb = x + (size_t)b * H * W * CI;

    // per-lane A ldmatrix offset (additive pitch-144, conflict-free)
    const uint32_t laneoA = (uint32_t)((lane & 15)*PITCH + ((lane >> 4) & 1)*16);
    // per-lane B gmem fragment base (bytes): co = warp_n*32 + lane/4, ci = (lane&3)*2
    const char* wbase = (const char*)g_w
        + ((warp_n*32 + (lane >> 2))*CI + (lane & 3)*2) * 2;

    float c[4][4][4];
    #pragma unroll
    for (int i = 0; i < 4; ++i)
        #pragma unroll
        for (int j = 0; j < 4; ++j)
            #pragma unroll
            for (int k = 0; k < 4; ++k) c[i][j][k] = 0.f;

    // ---- load one ks-step of B fragments (8 regs) from gmem ----
    auto load_Bks = [&](int t, int ks, uint32_t* dst) {
        const char* p = wbase + t*(CO*CI*2) + ks*32;
        #pragma unroll
        for (int nt = 0; nt < 4; ++nt) {
            dst[nt*2]   = *(const uint32_t*)(p + nt*(8*CI*2));        // ci k..k+1
            dst[nt*2+1] = *(const uint32_t*)(p + nt*(8*CI*2) + 16);   // ci k+8..k+9
        }
    };

    // ---- slab build (conv or edge), then the single barrier ----
    if (!is_edge) {
        for (int e = tid; e < SLAB_SLOTS*16; e += 512) {
            int c4   = e & 15;
            int slot = e >> 4;
            int hr   = slot / SLAB_WC;
            int wc   = slot - hr*SLAB_WC;
            int hrow = r0 + hr;
            int w    = 2*wc + (hrow & 1);
            float4 v = make_float4(0.f,0.f,0.f,0.f);
            if (hrow <= 208 && w <= 132)
                v = *(const float4*)(xb + ((size_t)hrow*W + w)*CI + c4*4);
            *(uint2*)(smem + slot*PITCH + c4*8) = cvt4(v);
        }
    } else {
        // zero the whole ow=128 output column (valid cells overwritten later)
        for (int e = tid; e < OHH*CO; e += 512) {
            int oh = e >> 7, co = e & 127;
            out[((size_t)(b*OHH + oh)*OWW + 128)*CO + co] = 0.f;
        }
        // edge slab: slot (wp, j): h = 2j + (wp&1), w = 128+wp; 5*132 slots
        for (int e = tid; e < 5*132*16; e += 512) {
            int c4   = e & 15;
            int slot = e >> 4;
            int wp   = slot / 132;
            int j    = slot - wp*132;
            int h    = 2*j + (wp & 1);
            float4 v = make_float4(0.f,0.f,0.f,0.f);
            if (h <= 208)
                v = *(const float4*)(xb + ((size_t)h*W + 128 + wp)*CI + c4*4);
            *(uint2*)(smem + slot*PITCH + c4*8) = cvt4(v);
        }
    }
    __syncthreads();   // the ONLY barrier

    // ---- barrier-free tap loop ----
    const bool active = !is_edge || (warp_m < 2);   // edge: warp_m>=2 idle
    if (active) {
        const int rp = (r0 + warp_m) & 1;
        uint32_t bb[2][8];
        load_Bks(0, 0, bb[0]);
        for (int t = 0; t < NTAP; ++t) {
            const int dh = c_dh[t], dw = c_dw[t];
            uint32_t a0;
            if (!is_edge) {
                const int hp  = (rp + dh) & 1;
                const int wc0 = (rp + dw - hp) >> 1;
                a0 = smem_base + (uint32_t)(((warp_m + dh)*SLAB_WC + wc0)*PITCH)
                   + (uint32_t)(warp_m*64*0) + laneoA;   // warp_m rows folded below
            } else {
                a0 = smem_base + (uint32_t)((dw*132 + (dh >> 1))*PITCH) + laneoA;
            }
            // conv: warp's 64 M-rows start at slab row (warp_m+dh)*68+wc0 and
            //       advance by mt*16 within the SAME input row's wc — handled
            //       by mt*16*PITCH below (rows are wc-contiguous slots).
            // edge: warp rows m = warp_m*64 + ... -> + warp_m*64*PITCH.
            if (is_edge) a0 += (uint32_t)(warp_m*64*PITCH);

            #pragma unroll
            for (int ks = 0; ks < 4; ++ks) {
                uint32_t* cur = bb[ks & 1];
                uint32_t* nxt = bb[(ks & 1) ^ 1];
                if (ks < 3)            load_Bks(t, ks + 1, nxt);
                else if (t + 1 < NTAP) load_Bks(t + 1, 0, nxt);
                uint32_t ah[4][4];
                #pragma unroll
                for (int mt = 0; mt < 4; ++mt)
                    LDSM4(ah[mt], a0 + (uint32_t)(mt*16*PITCH + ks*32));
                #pragma unroll
                for (int mt = 0; mt < 4; ++mt)
                    #pragma unroll
                    for (int nt = 0; nt < 4; ++nt)
                        MMA16816(c[mt][nt], ah[mt], cur[nt*2], cur[nt*2+1]);
            }
        }
    }

    // ---- epilogue ----
    const int co0 = warp_n*32 + (lane & 3)*2;
    if (!is_edge) {
        const int row = r0 + warp_m;
        if (row <= 200) {
            const int p   = row & 1;
            const int adi = row > 100 ? row - 100 : 100 - row;
            float* rbaseo = out + ((size_t)(b*OHH + row) * OWW) * CO;
            const float2 z2 = make_float2(0.f, 0.f);
            #pragma unroll
            for (int mt = 0; mt < 4; ++mt) {
                #pragma unroll
                for (int hf = 0; hf < 2; ++hf) {
                    int owc = mt*16 + (lane >> 2) + hf*8;
                    int ow  = 2*owc + p;
                    int owz = p ? (ow - 1) : (ow + 1);
                    int adj = ow > 64 ? ow - 64 : 64 - ow;
                    bool valid = (adi + adj) <= 128;
                    float* vb = rbaseo + (size_t)ow  * CO;
                    float* zb = rbaseo + (size_t)owz * CO;
                    #pragma unroll
                    for (int nt = 0; nt < 4; ++nt) {
                        int co = co0 + nt*8;
                        float v0 = c[mt][nt][hf*2+0] + s_off[co];
                        float v1 = c[mt][nt][hf*2+1] + s_off[co+1];
                        v0 = v0 > 0.f ? v0 : (__expf(v0) - 1.0f);
                        v1 = v1 > 0.f ? v1 : (__expf(v1) - 1.0f);
                        *(float2*)(vb + co) = valid ? make_float2(v0, v1) : z2;
                        *(float2*)(zb + co) = z2;
                    }
                }
            }
        }
    } else if (warp_m < 2) {
        // edge: row m -> oh=2m, ow=128; valid iff oh in [36,164]
        #pragma unroll
        for (int mt = 0; mt < 4; ++mt) {
            #pragma unroll
            for (int hf = 0; hf < 2; ++hf) {
                int m  = warp_m*64 + mt*16 + (lane >> 2) + hf*8;
                int oh = 2*m;
                if (m <= 100 && oh >= 36 && oh <= 164) {
                    float* vb = out + ((size_t)(b*OHH + oh)*OWW + 128)*CO;
                    #pragma unroll
                    for (int nt = 0; nt < 4; ++nt) {
                        int co = co0 + nt*8;
                        float v0 = c[mt][nt][hf*2+0] + s_off[co];
                        float v1 = c[mt][nt][hf*2+1] + s_off[co+1];
                        v0 = v0 > 0.f ? v0 : (__expf(v0) - 1.0f);
                        v1 = v1 > 0.f ? v1 : (__expf(v1) - 1.0f);
                        *(float2*)(vb + co) = make_float2(v0, v1);
                    }
                }
            }
        }
    }
}

extern "C" void kernel_launch(void* const* d_in, const int* in_sizes, int n_in,
                              void* d_out, int out_size) {
    const float* x      = (const float*)d_in[0];   // [16,209,133,64]
    const float* sw     = (const float*)d_in[1];   // [19*64*128] as [ci][co][t]
    const float* offset = (const float*)d_in[2];   // [128]
    float* out = (float*)d_out;

    cudaFuncSetAttribute(conv_mma_kernel,
                         cudaFuncAttributeMaxDynamicSharedMemorySize, SMEM_TOTAL);

    prep_w_kernel<<<(NTAP*CO*CI + 255)/256, 256>>>(sw);
    conv_mma_kernel<<<dim3(52, BATCH), 512, SMEM_TOTAL>>>(x, offset, out);
}

// round 12
// speedup vs baseline: 1.7188x; 1.7188x over previous
#include <cuda_runtime.h>
#include <cuda_fp16.h>
#include <cstdint>
#include <math.h>

#define BATCH 16
#define H 209
#define W 133
#define CI 64
#define CO 128
#define NTAP 19
#define OHH 201
#define OWW 129

// hex_indices(2) order (t matches sparse_weights layout) — validated in R1
__constant__ int c_dh[NTAP] = {4,3,5,6,5,3,2,1,2,4,6,7,8,7,6,4,2,1,0};
__constant__ int c_dw[NTAP] = {2,3,3,2,1,1,2,3,4,4,4,3,2,1,0,0,0,1,2};

// prepped weights: [t][co][ci] fp16
__device__ __align__(16) __half g_w[NTAP*CO*CI];

__device__ __forceinline__ uint32_t smem_u32(const void* p) {
    uint32_t a;
    asm("{ .reg .u64 t; cvta.to.shared.u64 t, %1; cvt.u32.u64 %0, t; }" : "=r"(a) : "l"(p));
    return a;
}
__device__ __forceinline__ uint32_t pack2h(__half a, __half b) {
    return (uint32_t)__half_as_ushort(a) | ((uint32_t)__half_as_ushort(b) << 16);
}
__device__ __forceinline__ uint2 cvt4(float4 v) {
    return make_uint2(pack2h(__float2half_rn(v.x), __float2half_rn(v.y)),
                      pack2h(__float2half_rn(v.z), __float2half_rn(v.w)));
}

#define LDSM4(r, addr)                                                          \
    asm volatile("ldmatrix.sync.aligned.m8n8.x4.shared.b16 {%0,%1,%2,%3}, [%4];"\
        : "=r"((r)[0]), "=r"((r)[1]), "=r"((r)[2]), "=r"((r)[3]) : "r"(addr))

#define MMA16816(c, a, b0, b1)                                                  \
    asm volatile("mma.sync.aligned.m16n8k16.row.col.f32.f16.f16.f32 "           \
        "{%0,%1,%2,%3}, {%4,%5,%6,%7}, {%8,%9}, {%0,%1,%2,%3};"                 \
        : "+f"((c)[0]), "+f"((c)[1]), "+f"((c)[2]), "+f"((c)[3])                \
        : "r"((a)[0]), "r"((a)[1]), "r"((a)[2]), "r"((a)[3]), "r"(b0), "r"(b1))

#define CP_ASYNC(dst, src, sz)                                                  \
    asm volatile("cp.async.cg.shared.global [%0], [%1], 16, %2;"                \
        :: "r"(dst), "l"(src), "r"(sz))
#define CP_COMMIT() asm volatile("cp.async.commit_group;" ::: "memory")
#define CP_WAIT(n)  asm volatile("cp.async.wait_group %0;" :: "n"(n) : "memory")
#define BARQ(id)    asm volatile("bar.sync %0, 128;" :: "r"(id) : "memory")

// ---------------- prep: weights to fp16, layout [t][co][ci] ----------------
__global__ void prep_w_kernel(const float* __restrict__ sw) {
    int i = blockIdx.x * blockDim.x + threadIdx.x;
    if (i >= NTAP*CO*CI) return;
    int ci = i & 63;
    int co = (i >> 6) & 127;
    int t  = i >> 13;
    g_w[i] = __float2half_rn(sw[(ci*CO + co)*NTAP + t]);
}

// ---------------- main mma.sync kernel ----------------
// grid (52, 16), 512 threads (16 warps: 4 M x 4 N). PITCH-144 additive layout.
// A: fp16 x-slab in smem, built once, ONE block barrier total.
// B: per-warp_n-QUARTET staging — the quartet's warp_m==0 cp.asyncs its own
//    32-row B slice (4.5KB) into a private 4-slot ring; quartet syncs with a
//    named 128-thread barrier. No block-wide barriers in the tap loop; the
//    four quartets free-run, interleaving LDSM and MMA phases.
// edge CTA (blockIdx.x==51): all-tap A slab (660 slots), same quartet-B scheme.
#define PITCH       144
#define SLAB_WC     68
#define SLAB_SLOTS  (12*SLAB_WC)            // 816 (conv) | edge uses 5*132=660
#define SLAB_BYTES  (SLAB_SLOTS*PITCH)      // 117504
#define BOFF        SLAB_BYTES
#define BSLICE      (32*PITCH)              // 4608 bytes per quartet slot
#define NRING       4
#define SMEM_TOTAL  (SLAB_BYTES + 4*NRING*BSLICE + 512)   // 191744

__global__ __launch_bounds__(512, 1)
void conv_mma_kernel(const float* __restrict__ x,
                     const float* __restrict__ off, float* __restrict__ out) {
    extern __shared__ __align__(1024) char smem[];
    const uint32_t smem_base = smem_u32(smem);
    const int tid    = threadIdx.x;
    const int lane   = tid & 31;
    const int wid    = tid >> 5;
    const int warp_m = wid >> 2;       // 0..3
    const int warp_n = wid & 3;        // 0..3
    const int b      = blockIdx.y;
    const bool is_edge = (blockIdx.x == 51);
    const int r0     = blockIdx.x * 4; // first output row (conv path)
    const int barid  = 4 + warp_n;     // named barrier per quartet

    float* s_off = (float*)(smem + SMEM_TOTAL - 512);
    if (tid < CO) s_off[tid] = off[tid];

    const float* xb = x + (size_t)b * H * W * CI;

    // per-lane A ldmatrix offset (additive pitch-144, conflict-free)
    const uint32_t laneoA = (uint32_t)((lane & 15)*PITCH + ((lane >> 4) & 1)*16);
    // per-lane B ldmatrix offset WITHIN the quartet's 32-row slice
    const uint32_t laneoB = (uint32_t)(((lane & 7) + ((lane >> 4) & 1)*8)*PITCH
                                        + ((lane >> 3) & 1)*16);
    // quartet's B ring base
    const uint32_t bring = smem_base + BOFF + (uint32_t)(warp_n*NRING*BSLICE);

    float c[4][4][4];
    #pragma unroll
    for (int i = 0; i < 4; ++i)
        #pragma unroll
        for (int j = 0; j < 4; ++j)
            #pragma unroll
            for (int k = 0; k < 4; ++k) c[i][j][k] = 0.f;

    // ---- producer (warp_m==0): stage this quartet's B slice for tap t ----
    auto issue_Bq = [&](int t) {
        uint32_t dst = bring + (uint32_t)((t & (NRING-1))*BSLICE);
        const __half* src = g_w + (size_t)t*CO*CI + (warp_n*32)*CI;
        #pragma unroll
        for (int i = 0; i < 8; ++i) {
            int e   = lane + i*32;       // 0..255: 32 rows x 8 c8
            int c8  = e & 7;
            int row = e >> 3;
            CP_ASYNC(dst + (uint32_t)(row*PITCH + c8*16),
                     src + row*CI + c8*8, 16);
        }
        CP_COMMIT();
    };

    // ---- compute one tap: A tile at a0 (additive), B slice slot base bq ----
    auto compute = [&](uint32_t a0, uint32_t bq) {
        const uint32_t b0 = bq + laneoB;
        #pragma unroll
        for (int ks = 0; ks < 4; ++ks) {
            uint32_t bh[2][4];
            #pragma unroll
            for (int q = 0; q < 2; ++q)
                LDSM4(bh[q], b0 + (uint32_t)(q*16*PITCH + ks*32));
            #pragma unroll
            for (int mt = 0; mt < 4; ++mt) {
                uint32_t ah[4];
                LDSM4(ah, a0 + (uint32_t)(mt*16*PITCH + ks*32));
                #pragma unroll
                for (int nt = 0; nt < 4; ++nt) {
                    int q = nt >> 1, h = (nt & 1)*2;
                    MMA16816(c[mt][nt], ah, bh[q][h], bh[q][h+1]);
                }
            }
        }
    };

    // ---- build A slab (conv: 12 rows x 68 wc | edge: 5 wp x 132 j) ----
    if (!is_edge) {
        for (int e = tid; e < SLAB_SLOTS*16; e += 512) {
            int c4   = e & 15;
            int slot = e >> 4;
            int hr   = slot / SLAB_WC;
            int wc   = slot - hr*SLAB_WC;
            int hrow = r0 + hr;
            int w    = 2*wc + (hrow & 1);
            float4 v = make_float4(0.f,0.f,0.f,0.f);
            if (hrow <= 208 && w <= 132)
                v = *(const float4*)(xb + ((size_t)hrow*W + w)*CI + c4*4);
            *(uint2*)(smem + slot*PITCH + c4*8) = cvt4(v);
        }
    } else {
        for (int e = tid; e < OHH*CO; e += 512) {   // zero ow=128 column
            int oh = e >> 7, co = e & 127;
            out[((size_t)(b*OHH + oh)*OWW + 128)*CO + co] = 0.f;
        }
        // edge slab: slot(wp, j): h = 2j + (wp&1), w = 128+wp  (dh ≡ dw mod 2)
        for (int e = tid; e < 5*132*16; e += 512) {
            int c4   = e & 15;
            int slot = e >> 4;
            int wp   = slot / 132;
            int j    = slot - wp*132;
            int h    = 2*j + (wp & 1);
            float4 v = make_float4(0.f,0.f,0.f,0.f);
            if (h <= 208)
                v = *(const float4*)(xb + ((size_t)h*W + 128 + wp)*CI + c4*4);
            *(uint2*)(smem + slot*PITCH + c4*8) = cvt4(v);
        }
    }
    // producers prefill their quartet's B ring (3 groups)
    if (warp_m == 0) { issue_Bq(0); issue_Bq(1); issue_Bq(2); }
    __syncthreads();   // the ONLY block-wide barrier

    // ---- tap loop: quartets free-run, synced by named barrier ----
    const int rp = (r0 + warp_m) & 1;
    for (int t = 0; t < NTAP; ++t) {
        if (warp_m == 0) {
            if      (t <= 16)      { CP_WAIT(2); }
            else if (t == 17)      { CP_WAIT(1); }
            else                   { CP_WAIT(0); }
        }
        BARQ(barid);                         // B slot t ready; slot t-1 free
        if (warp_m == 0 && t + 3 < NTAP) issue_Bq(t + 3);

        uint32_t a0;
        if (!is_edge) {
            const int dh = c_dh[t], dw = c_dw[t];
            const int hp  = (rp + dh) & 1;
            const int wc0 = (rp + dw - hp) >> 1;
            a0 = smem_base + (uint32_t)(((warp_m + dh)*SLAB_WC + wc0)*PITCH) + laneoA;
        } else {
            const int dh = c_dh[t], dw = c_dw[t];
            a0 = smem_base + (uint32_t)((dw*132 + (dh >> 1) + warp_m*64)*PITCH) + laneoA;
        }
        compute(a0, bring + (uint32_t)((t & (NRING-1))*BSLICE));
    }

    // ---- epilogue ----
    const int co0 = warp_n*32 + (lane & 3)*2;
    if (!is_edge) {
        const int row = r0 + warp_m;
        if (row <= 200) {
            const int p   = row & 1;
            const int adi = row > 100 ? row - 100 : 100 - row;
            float* rbaseo = out + ((size_t)(b*OHH + row) * OWW) * CO;
            const float2 z2 = make_float2(0.f, 0.f);
            #pragma unroll
            for (int mt = 0; mt < 4; ++mt) {
                #pragma unroll
                for (int hf = 0; hf < 2; ++hf) {
                    int owc = mt*16 + (lane >> 2) + hf*8;
                    int ow  = 2*owc + p;
                    int owz = p ? (ow - 1) : (ow + 1);
                    int adj = ow > 64 ? ow - 64 : 64 - ow;
                    bool valid = (adi + adj) <= 128;
                    float* vb = rbaseo + (size_t)ow  * CO;
                    float* zb = rbaseo + (size_t)owz * CO;
                    #pragma unroll
                    for (int nt = 0; nt < 4; ++nt) {
                        int co = co0 + nt*8;
                        float v0 = c[mt][nt][hf*2+0] + s_off[co];
                        float v1 = c[mt][nt][hf*2+1] + s_off[co+1];
                        v0 = v0 > 0.f ? v0 : (__expf(v0) - 1.0f);
                        v1 = v1 > 0.f ? v1 : (__expf(v1) - 1.0f);
                        *(float2*)(vb + co) = valid ? make_float2(v0, v1) : z2;
                        *(float2*)(zb + co) = z2;
                    }
                }
            }
        }
    } else {
        // edge: tile row m -> oh=2m, ow=128; valid iff oh in [36,164]
        #pragma unroll
        for (int mt = 0; mt < 4; ++mt) {
            #pragma unroll
            for (int hf = 0; hf < 2; ++hf) {
                int m  = warp_m*64 + mt*16 + (lane >> 2) + hf*8;
                int oh = 2*m;
                if (m <= 100 && oh >= 36 && oh <= 164) {
                    float* vb = out + ((size_t)(b*OHH + oh)*OWW + 128)*CO;
                    #pragma unroll
                    for (int nt = 0; nt < 4; ++nt) {
                        int co = co0 + nt*8;
                        float v0 = c[mt][nt][hf*2+0] + s_off[co];
                        float v1 = c[mt][nt][hf*2+1] + s_off[co+1];
                        v0 = v0 > 0.f ? v0 : (__expf(v0) - 1.0f);
                        v1 = v1 > 0.f ? v1 : (__expf(v1) - 1.0f);
                        *(float2*)(vb + co) = make_float2(v0, v1);
                    }
                }
            }
        }
    }
}

extern "C" void kernel_launch(void* const* d_in, const int* in_sizes, int n_in,
                              void* d_out, int out_size) {
    const float* x      = (const float*)d_in[0];   // [16,209,133,64]
    const float* sw     = (const float*)d_in[1];   // [19*64*128] as [ci][co][t]
    const float* offset = (const float*)d_in[2];   // [128]
    float* out = (float*)d_out;

    cudaFuncSetAttribute(conv_mma_kernel,
                         cudaFuncAttributeMaxDynamicSharedMemorySize, SMEM_TOTAL);

    prep_w_kernel<<<(NTAP*CO*CI + 255)/256, 256>>>(sw);
    conv_mma_kernel<<<dim3(52, BATCH), 512, SMEM_TOTAL>>>(x, offset, out);
}